// round 1
// baseline (speedup 1.0000x reference)
#include <cuda_runtime.h>
#include <cstdint>

// Problem shape (fixed by the dataset: setup_inputs uses B=2048, S=2048, H=64)
#define BB 2048
#define SS 2048
#define HH 64
#define EPSV 1e-6f
#define FULLMASK 0xFFFFFFFFu

typedef unsigned long long ull;

#define USE_F32X2 1

#if USE_F32X2
__device__ __forceinline__ ull fma2(ull a, ull b, ull c) {
    ull d;
    asm("fma.rn.f32x2 %0, %1, %2, %3;" : "=l"(d) : "l"(a), "l"(b), "l"(c));
    return d;
}
#else
__device__ __forceinline__ ull fma2(ull a, ull b, ull c) {
    float2 fa = *(float2*)&a, fb = *(float2*)&b, fc = *(float2*)&c;
    float2 fd;
    fd.x = fmaf(fa.x, fb.x, fc.x);
    fd.y = fmaf(fa.y, fb.y, fc.y);
    return *(ull*)&fd;
}
#endif

__device__ __forceinline__ float2 unpack2(ull a) {
    float2 r;
    asm("mov.b64 {%0, %1}, %2;" : "=f"(r.x), "=f"(r.y) : "l"(a));
    return r;
}

// sigma0 scratch (device global: allocation-free scratch per harness rules)
__device__ float g_sig0[BB];

// --------------------------------------------------------------------------
// Kernel 1: unbiased variance per row -> g_sig0[b] and out[b*S + 0]
// --------------------------------------------------------------------------
__global__ void __launch_bounds__(256) var_kernel(const float* __restrict__ res,
                                                  float* __restrict__ out) {
    int b = blockIdx.x;
    const float* row = res + (size_t)b * SS;
    float s = 0.f, s2 = 0.f;
    for (int i = threadIdx.x; i < SS; i += 256) {
        float v = row[i];
        s += v;
        s2 = fmaf(v, v, s2);
    }
#pragma unroll
    for (int o = 16; o; o >>= 1) {
        s  += __shfl_xor_sync(FULLMASK, s,  o);
        s2 += __shfl_xor_sync(FULLMASK, s2, o);
    }
    __shared__ float sh[16];
    int w = threadIdx.x >> 5, l = threadIdx.x & 31;
    if (l == 0) { sh[w] = s; sh[w + 8] = s2; }
    __syncthreads();
    if (threadIdx.x == 0) {
        float S1 = 0.f, S2 = 0.f;
#pragma unroll
        for (int i = 0; i < 8; i++) { S1 += sh[i]; S2 += sh[i + 8]; }
        float var = (S2 - S1 * S1 / (float)SS) / (float)(SS - 1);
        g_sig0[b] = var;
        out[(size_t)b * SS] = var;
    }
}

// --------------------------------------------------------------------------
// Kernel 2: the recurrence. One warp = 2 batch rows. W_hh rows in registers
// (packed f32x2 along k), h ping-pong in per-warp shared, broadcast LDS.128.
// Lane l owns output rows l and l+32.
// --------------------------------------------------------------------------
__global__ void __launch_bounds__(128) rnn_kernel(
    const float* __restrict__ res,   // [B][S]
    const float* __restrict__ Wih,   // [64][2]
    const float* __restrict__ bih,   // [64]
    const float* __restrict__ Whh,   // [64][64]
    const float* __restrict__ bhh,   // [64]
    const float* __restrict__ fcw,   // [64]
    const float* __restrict__ fcb1,  // [1]
    float* __restrict__ out)         // [B][S]
{
    const int lane = threadIdx.x & 31;
    const int wip  = threadIdx.x >> 5;              // warp in block (0..3)
    const int wg   = blockIdx.x * 4 + wip;          // global warp (0..1023)
    const int b0   = 2 * wg, b1 = 2 * wg + 1;
    const int r0   = lane, r1 = lane + 32;

    // W_hh rows for this lane, packed as f32x2 pairs along k (direct reinterpret)
    ull w0[32], w1[32];
    {
        const ull* p0 = (const ull*)(Whh + r0 * HH);
        const ull* p1 = (const ull*)(Whh + r1 * HH);
#pragma unroll
        for (int i = 0; i < 32; i++) { w0[i] = p0[i]; w1[i] = p1[i]; }
    }
    const float wih00 = Wih[r0 * 2], wih01 = Wih[r0 * 2 + 1];
    const float wih10 = Wih[r1 * 2], wih11 = Wih[r1 * 2 + 1];
    const float bb0 = bih[r0] + bhh[r0];
    const float bb1 = bih[r1] + bhh[r1];
    const float fc0 = fcw[r0], fc1 = fcw[r1];
    const float fcb = fcb1[0];

    // [warp][pingpong][batch-of-2][64] ; 4 KB static
    __shared__ __align__(16) float hbuf[4][2][2][HH];

    // h0 = 0
    hbuf[wip][0][0][r0] = 0.f; hbuf[wip][0][0][r1] = 0.f;
    hbuf[wip][0][1][r0] = 0.f; hbuf[wip][0][1][r1] = 0.f;
    __syncwarp();

    float sigA = g_sig0[b0];
    float sigB = g_sig0[b1];
    const float* resA = res + (size_t)b0 * SS;
    const float* resB = res + (size_t)b1 * SS;
    float* outA = out + (size_t)b0 * SS;
    float* outB = out + (size_t)b1 * SS;

    float eA = resA[0], eB = resB[0];
    int p = 0;

#pragma unroll 1
    for (int t = 1; t < SS; ++t) {
        const float e2a = eA * eA, e2b = eB * eB;
        // prefetch next eps (valid index; last iter value unused)
        eA = resA[t]; eB = resB[t];

        const float* hA = hbuf[wip][p][0];
        const float* hB = hbuf[wip][p][1];

        ull a0a = 0ull, a1a = 0ull, a0b = 0ull, a1b = 0ull;
#pragma unroll
        for (int i = 0; i < 16; i++) {
            ulonglong2 ha = *(const ulonglong2*)(hA + 4 * i);  // LDS.128 broadcast
            ulonglong2 hb = *(const ulonglong2*)(hB + 4 * i);
            a0a = fma2(w0[2 * i],     ha.x, a0a);
            a1a = fma2(w1[2 * i],     ha.x, a1a);
            a0b = fma2(w0[2 * i],     hb.x, a0b);
            a1b = fma2(w1[2 * i],     hb.x, a1b);
            a0a = fma2(w0[2 * i + 1], ha.y, a0a);
            a1a = fma2(w1[2 * i + 1], ha.y, a1a);
            a0b = fma2(w0[2 * i + 1], hb.y, a0b);
            a1b = fma2(w1[2 * i + 1], hb.y, a1b);
        }

        float2 u;
        u = unpack2(a0a);
        const float h0a = (u.x + u.y) + fmaf(e2a, wih00, fmaf(sigA, wih01, bb0));
        u = unpack2(a1a);
        const float h1a = (u.x + u.y) + fmaf(e2a, wih10, fmaf(sigA, wih11, bb1));
        u = unpack2(a0b);
        const float h0b = (u.x + u.y) + fmaf(e2b, wih00, fmaf(sigB, wih01, bb0));
        u = unpack2(a1b);
        const float h1b = (u.x + u.y) + fmaf(e2b, wih10, fmaf(sigB, wih11, bb1));

        // publish new h first, so next-step matvec work is ready before the
        // serial sigma tail (reduction + softplus) resolves
        float* nA = hbuf[wip][p ^ 1][0];
        float* nB = hbuf[wip][p ^ 1][1];
        nA[r0] = h0a; nA[r1] = h1a;
        nB[r0] = h0b; nB[r1] = h1b;
        __syncwarp();

        // sigma = softplus(h_new . fc + fcb) + eps
        float pa = fmaf(h0a, fc0, h1a * fc1);
        float pb = fmaf(h0b, fc0, h1b * fc1);
#pragma unroll
        for (int o = 16; o; o >>= 1) {
            pa += __shfl_xor_sync(FULLMASK, pa, o);
            pb += __shfl_xor_sync(FULLMASK, pb, o);
        }
        // even lanes compute batch A's softplus, odd lanes batch B's
        const float x  = ((lane & 1) ? pb : pa) + fcb;
        const float sp = fmaxf(x, 0.f) + log1pf(expf(-fabsf(x)));
        const float sig = sp + EPSV;
        sigA = __shfl_sync(FULLMASK, sig, 0);
        sigB = __shfl_sync(FULLMASK, sig, 1);

        if (lane < 2) { (lane ? outB : outA)[t] = sig; }

        p ^= 1;
    }
}

// --------------------------------------------------------------------------
extern "C" void kernel_launch(void* const* d_in, const int* in_sizes, int n_in,
                              void* d_out, int out_size) {
    const float* res  = (const float*)d_in[0];
    const float* Wih  = (const float*)d_in[1];
    const float* bih  = (const float*)d_in[2];
    const float* Whh  = (const float*)d_in[3];
    const float* bhh  = (const float*)d_in[4];
    const float* fcw  = (const float*)d_in[5];
    const float* fcb  = (const float*)d_in[6];
    float* out = (float*)d_out;

    var_kernel<<<BB, 256>>>(res, out);
    rnn_kernel<<<BB / 8, 128>>>(res, Wih, bih, Whh, bhh, fcw, fcb, out);
}